// round 11
// baseline (speedup 1.0000x reference)
#include <cuda_runtime.h>

#define NN 50000
#define EE 500000
#define HH 128
#define GG 100
#define NPG 500
#define NPROT 400
#define PNF 35
#define LNF 11
#define DINE 261
#define EPSBN 1e-5f

// ---------------- scratch (static device globals; allocation-free) ----------------
__device__ float g_h[(size_t)NN * HH];
__device__ float g_agg[(size_t)NN * HH];
__device__ float g_P[(size_t)NN * HH];
__device__ float g_Q[(size_t)NN * HH];
__device__ float g_pos[NN * 3];
__device__ float g_posagg[NN * 3];
__device__ float g_deg[NN];
__device__ float g_bnsum[HH];
__device__ float g_bnsq[HH];
// packed tf32 weights (hi/lo split) for mma: [L][16 ks][16 nt][32 lane][2]
__device__ __align__(16) float g_W2Ph[4 * 16384];
__device__ __align__(16) float g_W2Pl[4 * 16384];
__device__ __align__(16) float g_C1Ph[4 * 16384];
__device__ __align__(16) float g_C1Pl[4 * 16384];

// ---------------- helpers ----------------
union F2 {
    float2 f;
    unsigned long long u;
};

__device__ __forceinline__ void ffma2(F2& d, F2 a, F2 b) {
    asm("fma.rn.f32x2 %0, %1, %2, %0;" : "+l"(d.u) : "l"(a.u), "l"(b.u));
}

__device__ __forceinline__ float siluf(float x) {
    return x * (1.0f / (1.0f + __expf(-x)));
}
__device__ __forceinline__ float2 silu2(F2 v) {
    return make_float2(siluf(v.f.x), siluf(v.f.y));
}

__device__ __forceinline__ unsigned f2tf(float x) {
    unsigned r;
    asm("cvt.rna.tf32.f32 %0, %1;" : "=r"(r) : "f"(x));
    return r;
}

__device__ __forceinline__ void mma_tf32(float* c, unsigned a0, unsigned a1, unsigned a2, unsigned a3,
                                         unsigned b0, unsigned b1) {
    asm volatile("mma.sync.aligned.m16n8k8.row.col.f32.tf32.tf32.f32 "
                 "{%0,%1,%2,%3}, {%4,%5,%6,%7}, {%8,%9}, {%0,%1,%2,%3};"
                 : "+f"(c[0]), "+f"(c[1]), "+f"(c[2]), "+f"(c[3])
                 : "r"(a0), "r"(a1), "r"(a2), "r"(a3), "r"(b0), "r"(b1));
}

// ---------------- setup kernels ----------------
__global__ void k_init(const float* __restrict__ pos) {
    int i = blockIdx.x * blockDim.x + threadIdx.x;
    if (i < NN * 3) g_pos[i] = pos[i];
    if (i < NN) g_deg[i] = 0.0f;
    if (i < HH) { g_bnsum[i] = 0.0f; g_bnsq[i] = 0.0f; }
}

__global__ void k_deg(const int* __restrict__ ei) {
    int i = blockIdx.x * blockDim.x + threadIdx.x;
    if (i < EE) atomicAdd(&g_deg[ei[i]], 1.0f);
}

__global__ void __launch_bounds__(128) k_proj(const float* __restrict__ x,
                                              const float* __restrict__ Wp, const float* __restrict__ bp,
                                              const float* __restrict__ Wl, const float* __restrict__ bl) {
    __shared__ float xs[64][PNF];
    const int tid = threadIdx.x;
    const int base = blockIdx.x * 64;
    for (int i = tid; i < 64 * PNF; i += 128) {
        int n = i / PNF, k = i - n * PNF;
        xs[n][k] = (base + n < NN) ? x[(size_t)(base + n) * PNF + k] : 0.0f;
    }
    __syncthreads();
    float s = 0.0f, sq = 0.0f;
    for (int n = 0; n < 64; n++) {
        int gn = base + n;
        if (gn >= NN) break;
        bool prot = (gn % NPG) < NPROT;
        float acc;
        if (prot) {
            acc = bp[tid];
            #pragma unroll
            for (int k = 0; k < PNF; k++) acc += xs[n][k] * Wp[k * HH + tid];
        } else {
            acc = bl[tid];
            #pragma unroll
            for (int k = 0; k < LNF; k++) acc += xs[n][k] * Wl[k * HH + tid];
        }
        g_h[(size_t)gn * HH + tid] = acc;
        s += acc;
        sq += acc * acc;
    }
    atomicAdd(&g_bnsum[tid], s);
    atomicAdd(&g_bnsq[tid], sq);
}

__global__ void k_bn(const float* __restrict__ gamma, const float* __restrict__ beta) {
    size_t i = (size_t)blockIdx.x * blockDim.x + threadIdx.x;
    if (i >= (size_t)NN * HH) return;
    int t = (int)(i & (HH - 1));
    float mu = g_bnsum[t] * (1.0f / NN);
    float var = g_bnsq[t] * (1.0f / NN) - mu * mu;
    g_h[i] = (g_h[i] - mu) * rsqrtf(var + EPSBN) * gamma[t] + beta[t];
}

__global__ void k_zero() {
    size_t i = (size_t)blockIdx.x * blockDim.x + threadIdx.x;
    if (i < (size_t)NN * HH) g_agg[i] = 0.0f;
    if (i < NN * 3) g_posagg[i] = 0.0f;
}

// pack e_w2 and c_w1 into mma-B fragment order, split hi/lo tf32.
// q-layout: [16 ks][16 nt][32 lane][2]; element = W[8ks + lane%4 + 4i][8nt + lane/4]
__global__ void k_pack(const float* __restrict__ ew2, const float* __restrict__ cw1) {
    int idx = blockIdx.x * blockDim.x + threadIdx.x;
    if (idx >= 2 * 4 * 16384) return;
    int m = idx >> 16;
    int r = idx & 65535;
    int l = r >> 14;
    int q = r & 16383;
    int ks = q >> 10;
    int t = q & 1023;
    int nt = t >> 6;
    int u = t & 63;
    int lane = u >> 1;
    int i = u & 1;
    int k = 8 * ks + (lane & 3) + 4 * i;
    int n = 8 * nt + (lane >> 2);
    const float* src = (m == 0 ? ew2 : cw1);
    float v = src[(size_t)l * HH * HH + (size_t)k * HH + n];
    unsigned hi = f2tf(v);
    unsigned lo = f2tf(v - __uint_as_float(hi));
    size_t off = (size_t)l * 16384 + q;
    if (m == 0) { g_W2Ph[off] = __uint_as_float(hi); g_W2Pl[off] = __uint_as_float(lo); }
    else        { g_C1Ph[off] = __uint_as_float(hi); g_C1Pl[off] = __uint_as_float(lo); }
}

// ---------------- per-layer node precompute: P = h@W1a + b1, Q = h@W1b ----------------
__global__ void __launch_bounds__(128) k_nodepre(const float* __restrict__ W1,
                                                 const float* __restrict__ b1) {
    __shared__ float2 Hs[16 * 128];
    const int tid = threadIdx.x;
    const int base = blockIdx.x * 32;
    #pragma unroll 4
    for (int p = 0; p < 16; p++) {
        int n0 = base + 2 * p, n1 = base + 2 * p + 1;
        if (n0 > NN - 1) n0 = NN - 1;
        if (n1 > NN - 1) n1 = NN - 1;
        Hs[p * 128 + tid] = make_float2(g_h[(size_t)n0 * HH + tid], g_h[(size_t)n1 * HH + tid]);
    }
    __syncthreads();
    const int ln = tid & 31;
    const int pg = (tid >> 5) * 4;
    F2 acc[16];

    #pragma unroll
    for (int j = 0; j < 4; j++) {
        float b = b1[ln + 32 * j];
        #pragma unroll
        for (int p = 0; p < 4; p++) acc[p * 4 + j].f = make_float2(b, b);
    }
    #pragma unroll 2
    for (int k = 0; k < 128; k++) {
        F2 w[4];
        #pragma unroll
        for (int j = 0; j < 4; j++) { float v = W1[k * HH + ln + 32 * j]; w[j].f = make_float2(v, v); }
        #pragma unroll
        for (int p = 0; p < 4; p++) {
            F2 v; v.f = Hs[(pg + p) * 128 + k];
            #pragma unroll
            for (int j = 0; j < 4; j++) ffma2(acc[p * 4 + j], v, w[j]);
        }
    }
    #pragma unroll
    for (int p = 0; p < 4; p++) {
        int n0 = base + 2 * (pg + p), n1 = n0 + 1;
        #pragma unroll
        for (int j = 0; j < 4; j++) {
            if (n0 < NN) g_P[(size_t)n0 * HH + ln + 32 * j] = acc[p * 4 + j].f.x;
            if (n1 < NN) g_P[(size_t)n1 * HH + ln + 32 * j] = acc[p * 4 + j].f.y;
        }
    }

    #pragma unroll
    for (int i = 0; i < 16; i++) acc[i].f = make_float2(0.0f, 0.0f);
    const float* W1b = W1 + 128 * HH;
    #pragma unroll 2
    for (int k = 0; k < 128; k++) {
        F2 w[4];
        #pragma unroll
        for (int j = 0; j < 4; j++) { float v = W1b[k * HH + ln + 32 * j]; w[j].f = make_float2(v, v); }
        #pragma unroll
        for (int p = 0; p < 4; p++) {
            F2 v; v.f = Hs[(pg + p) * 128 + k];
            #pragma unroll
            for (int j = 0; j < 4; j++) ffma2(acc[p * 4 + j], v, w[j]);
        }
    }
    #pragma unroll
    for (int p = 0; p < 4; p++) {
        int n0 = base + 2 * (pg + p), n1 = n0 + 1;
        #pragma unroll
        for (int j = 0; j < 4; j++) {
            if (n0 < NN) g_Q[(size_t)n0 * HH + ln + 32 * j] = acc[p * 4 + j].f.x;
            if (n1 < NN) g_Q[(size_t)n1 * HH + ln + 32 * j] = acc[p * 4 + j].f.y;
        }
    }
}

// ---------------- fused edge kernel (3xTF32 tensor cores for W2/C1 GEMMs) ----------------
// 32 edges/block, 128 threads = 4 warps. Warp w: m-tile (w&1)*16, n-range (w>>1)*64.
// Each GEMM uses the error-compensated split: Ahi@Whi + Alo@Whi + Ahi@Wlo (~fp32 accurate).
__global__ void __launch_bounds__(128) k_edge(
    const int* __restrict__ ei, const float* __restrict__ eattr,
    const float* __restrict__ W1tail,
    const float* __restrict__ b2, const float* __restrict__ cb1,
    const float* __restrict__ C2, int layer) {
    __shared__ float sA[32][132];
    __shared__ float sM[32][132];
    __shared__ float sREL[3][32];
    __shared__ float sD2[32];
    __shared__ float sEA[4][32];
    __shared__ float WS[32];
    __shared__ int RI[32], CI[32];

    const int tid = threadIdx.x;
    const int eb = blockIdx.x * 32;

    if (tid < 32) { RI[tid] = ei[eb + tid]; CI[tid] = ei[EE + eb + tid]; }
    {
        int e = tid >> 2, j = tid & 3;
        sEA[j][e] = eattr[(size_t)eb * 4 + tid];
    }
    __syncthreads();

    if (tid < 32) {
        int r = RI[tid], c = CI[tid];
        float rx = g_pos[r * 3 + 0] - g_pos[c * 3 + 0];
        float ry = g_pos[r * 3 + 1] - g_pos[c * 3 + 1];
        float rz = g_pos[r * 3 + 2] - g_pos[c * 3 + 2];
        sREL[0][tid] = rx; sREL[1][tid] = ry; sREL[2][tid] = rz;
        sD2[tid] = rx * rx + ry * ry + rz * rz;
    }
    __syncthreads();

    // ---- hid phase: thread = feature
    {
        float wd  = W1tail[tid];
        float we0 = W1tail[128 + tid];
        float we1 = W1tail[256 + tid];
        float we2 = W1tail[384 + tid];
        float we3 = W1tail[512 + tid];
        #pragma unroll 4
        for (int e = 0; e < 32; e++) {
            int r = RI[e], c = CI[e];
            float v = g_P[(size_t)r * HH + tid] + g_Q[(size_t)c * HH + tid]
                    + sD2[e] * wd + sEA[0][e] * we0 + sEA[1][e] * we1
                    + sEA[2][e] * we2 + sEA[3][e] * we3;
            sA[e][tid] = siluf(v);
        }
    }
    __syncthreads();

    const int lane = tid & 31;
    const int w = tid >> 5;
    const int mb = (w & 1) * 16;
    const int nb = (w >> 1) * 64;
    const int gq = lane >> 2;
    const int tq = lane & 3;
    const float* W2h = g_W2Ph + (size_t)layer * 16384;
    const float* W2l = g_W2Pl + (size_t)layer * 16384;
    const float* C1h = g_C1Ph + (size_t)layer * 16384;
    const float* C1l = g_C1Pl + (size_t)layer * 16384;
    const int ntb = nb >> 3;

    float acc[8][4];

    // ---- GEMM2: m = silu(hid @ W2 + b2)
    #pragma unroll
    for (int j = 0; j < 8; j++)
        #pragma unroll
        for (int i = 0; i < 4; i++) acc[j][i] = 0.0f;
    #pragma unroll 2
    for (int ks = 0; ks < 16; ks++) {
        int c0 = 8 * ks + tq;
        float x0 = sA[mb + gq][c0];
        float x1 = sA[mb + gq + 8][c0];
        float x2 = sA[mb + gq][c0 + 4];
        float x3 = sA[mb + gq + 8][c0 + 4];
        unsigned h0 = f2tf(x0), h1 = f2tf(x1), h2 = f2tf(x2), h3 = f2tf(x3);
        unsigned l0 = f2tf(x0 - __uint_as_float(h0));
        unsigned l1 = f2tf(x1 - __uint_as_float(h1));
        unsigned l2 = f2tf(x2 - __uint_as_float(h2));
        unsigned l3 = f2tf(x3 - __uint_as_float(h3));
        #pragma unroll
        for (int j = 0; j < 8; j++) {
            size_t boff = (size_t)(ks * 16 + ntb + j) * 64 + lane * 2;
            float2 bh = *(const float2*)&W2h[boff];
            float2 bl = *(const float2*)&W2l[boff];
            unsigned bh0 = __float_as_uint(bh.x), bh1 = __float_as_uint(bh.y);
            mma_tf32(acc[j], h0, h1, h2, h3, bh0, bh1);
            mma_tf32(acc[j], l0, l1, l2, l3, bh0, bh1);
            mma_tf32(acc[j], h0, h1, h2, h3, __float_as_uint(bl.x), __float_as_uint(bl.y));
        }
    }
    #pragma unroll
    for (int j = 0; j < 8; j++) {
        int n0 = nb + 8 * j + 2 * tq;
        float bA = b2[n0], bB = b2[n0 + 1];
        sM[mb + gq][n0]         = siluf(acc[j][0] + bA);
        sM[mb + gq][n0 + 1]     = siluf(acc[j][1] + bB);
        sM[mb + gq + 8][n0]     = siluf(acc[j][2] + bA);
        sM[mb + gq + 8][n0 + 1] = siluf(acc[j][3] + bB);
    }
    __syncthreads();

    // ---- C1 GEMM: gh = silu(m @ C1 + cb1) -> sA
    #pragma unroll
    for (int j = 0; j < 8; j++)
        #pragma unroll
        for (int i = 0; i < 4; i++) acc[j][i] = 0.0f;
    #pragma unroll 2
    for (int ks = 0; ks < 16; ks++) {
        int c0 = 8 * ks + tq;
        float x0 = sM[mb + gq][c0];
        float x1 = sM[mb + gq + 8][c0];
        float x2 = sM[mb + gq][c0 + 4];
        float x3 = sM[mb + gq + 8][c0 + 4];
        unsigned h0 = f2tf(x0), h1 = f2tf(x1), h2 = f2tf(x2), h3 = f2tf(x3);
        unsigned l0 = f2tf(x0 - __uint_as_float(h0));
        unsigned l1 = f2tf(x1 - __uint_as_float(h1));
        unsigned l2 = f2tf(x2 - __uint_as_float(h2));
        unsigned l3 = f2tf(x3 - __uint_as_float(h3));
        #pragma unroll
        for (int j = 0; j < 8; j++) {
            size_t boff = (size_t)(ks * 16 + ntb + j) * 64 + lane * 2;
            float2 bh = *(const float2*)&C1h[boff];
            float2 bl = *(const float2*)&C1l[boff];
            unsigned bh0 = __float_as_uint(bh.x), bh1 = __float_as_uint(bh.y);
            mma_tf32(acc[j], h0, h1, h2, h3, bh0, bh1);
            mma_tf32(acc[j], l0, l1, l2, l3, bh0, bh1);
            mma_tf32(acc[j], h0, h1, h2, h3, __float_as_uint(bl.x), __float_as_uint(bl.y));
        }
    }
    #pragma unroll
    for (int j = 0; j < 8; j++) {
        int n0 = nb + 8 * j + 2 * tq;
        float bA = cb1[n0], bB = cb1[n0 + 1];
        sA[mb + gq][n0]         = siluf(acc[j][0] + bA);
        sA[mb + gq][n0 + 1]     = siluf(acc[j][1] + bB);
        sA[mb + gq + 8][n0]     = siluf(acc[j][2] + bA);
        sA[mb + gq + 8][n0 + 1] = siluf(acc[j][3] + bB);
    }
    __syncthreads();

    // ---- w_e = gh . C2 (warp w handles edges 8w..8w+7)
    {
        float c2a = C2[lane], c2b = C2[lane + 32], c2c = C2[lane + 64], c2d = C2[lane + 96];
        #pragma unroll
        for (int i = 0; i < 8; i++) {
            int e = w * 8 + i;
            float s = sA[e][lane] * c2a + sA[e][lane + 32] * c2b
                    + sA[e][lane + 64] * c2c + sA[e][lane + 96] * c2d;
            #pragma unroll
            for (int o = 16; o; o >>= 1) s += __shfl_xor_sync(0xffffffffu, s, o);
            if (lane == 0) WS[e] = s;
        }
    }
    __syncthreads();

    // ---- scatter: agg[row] += m ; posagg[row] += rel * w
    #pragma unroll 4
    for (int e = 0; e < 32; e++) {
        atomicAdd(&g_agg[(size_t)RI[e] * HH + tid], sM[e][tid]);
    }
    if (tid < 96) {
        int e = tid / 3, c = tid - 3 * e;
        atomicAdd(&g_posagg[RI[e] * 3 + c], sREL[c][e] * WS[e]);
    }
}

// ---------------- fused node kernel ----------------
__global__ void __launch_bounds__(128) k_node(
    const float* __restrict__ NW1, const float* __restrict__ nb1,
    const float* __restrict__ NW2, const float* __restrict__ nb2) {
    __shared__ float2 A[16 * 128];
    __shared__ float2 Bs[16 * 128];
    const int tid = threadIdx.x;
    const int base = blockIdx.x * 32;

    if (tid < 96) {
        int n = base + tid / 3, c = tid % 3;
        if (n < NN) {
            float d = fmaxf(g_deg[n], 1.0f);
            g_pos[n * 3 + c] += g_posagg[n * 3 + c] / d;
        }
    }

    #pragma unroll 4
    for (int p = 0; p < 16; p++) {
        int n0 = base + 2 * p, n1 = base + 2 * p + 1;
        if (n0 > NN - 1) n0 = NN - 1;
        if (n1 > NN - 1) n1 = NN - 1;
        A[p * 128 + tid]  = make_float2(g_h[(size_t)n0 * HH + tid], g_h[(size_t)n1 * HH + tid]);
        Bs[p * 128 + tid] = make_float2(g_agg[(size_t)n0 * HH + tid], g_agg[(size_t)n1 * HH + tid]);
    }
    __syncthreads();

    const int ln = tid & 31;
    const int pg = (tid >> 5) * 4;
    F2 acc[16];

    #pragma unroll
    for (int j = 0; j < 4; j++) {
        float b = nb1[ln + 32 * j];
        #pragma unroll
        for (int p = 0; p < 4; p++) acc[p * 4 + j].f = make_float2(b, b);
    }
    #pragma unroll 2
    for (int k = 0; k < 128; k++) {
        F2 w[4];
        #pragma unroll
        for (int j = 0; j < 4; j++) { float v = NW1[k * HH + ln + 32 * j]; w[j].f = make_float2(v, v); }
        #pragma unroll
        for (int p = 0; p < 4; p++) {
            F2 v; v.f = A[(pg + p) * 128 + k];
            #pragma unroll
            for (int j = 0; j < 4; j++) ffma2(acc[p * 4 + j], v, w[j]);
        }
    }
    #pragma unroll 2
    for (int k = 0; k < 128; k++) {
        F2 w[4];
        #pragma unroll
        for (int j = 0; j < 4; j++) { float v = NW1[(128 + k) * HH + ln + 32 * j]; w[j].f = make_float2(v, v); }
        #pragma unroll
        for (int p = 0; p < 4; p++) {
            F2 v; v.f = Bs[(pg + p) * 128 + k];
            #pragma unroll
            for (int j = 0; j < 4; j++) ffma2(acc[p * 4 + j], v, w[j]);
        }
    }
    __syncthreads();
    #pragma unroll
    for (int p = 0; p < 4; p++)
        #pragma unroll
        for (int j = 0; j < 4; j++)
            Bs[(pg + p) * 128 + ln + 32 * j] = silu2(acc[p * 4 + j]);
    __syncthreads();

    #pragma unroll
    for (int j = 0; j < 4; j++) {
        float b = nb2[ln + 32 * j];
        #pragma unroll
        for (int p = 0; p < 4; p++) acc[p * 4 + j].f = make_float2(b, b);
    }
    #pragma unroll 2
    for (int k = 0; k < 128; k++) {
        F2 w[4];
        #pragma unroll
        for (int j = 0; j < 4; j++) { float v = NW2[k * HH + ln + 32 * j]; w[j].f = make_float2(v, v); }
        #pragma unroll
        for (int p = 0; p < 4; p++) {
            F2 v; v.f = Bs[(pg + p) * 128 + k];
            #pragma unroll
            for (int j = 0; j < 4; j++) ffma2(acc[p * 4 + j], v, w[j]);
        }
    }
    #pragma unroll
    for (int p = 0; p < 4; p++) {
        int n0 = base + 2 * (pg + p), n1 = n0 + 1;
        #pragma unroll
        for (int j = 0; j < 4; j++) {
            if (n0 < NN) g_h[(size_t)n0 * HH + ln + 32 * j] += acc[p * 4 + j].f.x;
            if (n1 < NN) g_h[(size_t)n1 * HH + ln + 32 * j] += acc[p * 4 + j].f.y;
        }
    }
}

// ---------------- pooling + MLP head ----------------
__global__ void __launch_bounds__(128) k_head(
    const float* __restrict__ h1w, const float* __restrict__ h1b,
    const float* __restrict__ h2w, const float* __restrict__ h2b,
    const float* __restrict__ h3w, const float* __restrict__ h3b,
    float* __restrict__ out) {
    __shared__ float gf[256];
    __shared__ float z1[128];
    __shared__ float z2[64];
    const int g = blockIdx.x, t = threadIdx.x;
    const float* hp = g_h + (size_t)g * NPG * HH;
    float s = 0.0f;
    #pragma unroll 4
    for (int i = 0; i < NPG; i++) s += hp[(size_t)i * HH + t];
    gf[t] = s;
    gf[128 + t] = s * (1.0f / (float)NPG);
    __syncthreads();
    float acc = h1b[t];
    #pragma unroll 4
    for (int k = 0; k < 256; k++) acc += gf[k] * h1w[k * 128 + t];
    z1[t] = fmaxf(acc, 0.0f);
    __syncthreads();
    if (t < 64) {
        float a = h2b[t];
        #pragma unroll 4
        for (int k = 0; k < 128; k++) a += z1[k] * h2w[k * 64 + t];
        z2[t] = fmaxf(a, 0.0f);
    }
    __syncthreads();
    if (t == 0) {
        float a = h3b[0];
        #pragma unroll
        for (int k = 0; k < 64; k++) a += z2[k] * h3w[k];
        out[g] = a;
    }
}

// ---------------- launcher ----------------
extern "C" void kernel_launch(void* const* d_in, const int* in_sizes, int n_in,
                              void* d_out, int out_size) {
    const float* x    = (const float*)d_in[0];
    const float* pos  = (const float*)d_in[1];
    const int*   ei   = (const int*)d_in[2];
    const float* ea   = (const float*)d_in[3];
    const float* Wp   = (const float*)d_in[6];
    const float* bp   = (const float*)d_in[7];
    const float* Wl   = (const float*)d_in[8];
    const float* bl   = (const float*)d_in[9];
    const float* gam  = (const float*)d_in[10];
    const float* bet  = (const float*)d_in[11];
    const float* ew1  = (const float*)d_in[12];
    const float* eb1  = (const float*)d_in[13];
    const float* ew2  = (const float*)d_in[14];
    const float* eb2  = (const float*)d_in[15];
    const float* cw1  = (const float*)d_in[16];
    const float* cb1  = (const float*)d_in[17];
    const float* cw2  = (const float*)d_in[18];
    const float* nw1  = (const float*)d_in[19];
    const float* nb1  = (const float*)d_in[20];
    const float* nw2  = (const float*)d_in[21];
    const float* nb2  = (const float*)d_in[22];
    const float* h1w  = (const float*)d_in[23];
    const float* h1b  = (const float*)d_in[24];
    const float* h2w  = (const float*)d_in[25];
    const float* h2b  = (const float*)d_in[26];
    const float* h3w  = (const float*)d_in[27];
    const float* h3b  = (const float*)d_in[28];
    float* out = (float*)d_out;

    k_init<<<(NN * 3 + 255) / 256, 256>>>(pos);
    k_proj<<<(NN + 63) / 64, 128>>>(x, Wp, bp, Wl, bl);
    k_deg<<<(EE + 255) / 256, 256>>>(ei);
    k_bn<<<(int)(((size_t)NN * HH + 255) / 256), 256>>>(gam, bet);
    k_pack<<<(2 * 4 * 16384 + 255) / 256, 256>>>(ew2, cw1);

    for (int l = 0; l < 4; l++) {
        k_zero<<<(int)(((size_t)NN * HH + 255) / 256), 256>>>();
        k_nodepre<<<(NN + 31) / 32, 128>>>(ew1 + (size_t)l * DINE * HH, eb1 + l * HH);
        k_edge<<<EE / 32, 128>>>(ei, ea,
                                 ew1 + (size_t)l * DINE * HH + 256 * HH,
                                 eb2 + l * HH, cb1 + l * HH,
                                 cw2 + (size_t)l * HH, l);
        k_node<<<(NN + 31) / 32, 128>>>(nw1 + (size_t)l * 2 * HH * HH, nb1 + l * HH,
                                        nw2 + (size_t)l * HH * HH,     nb2 + l * HH);
    }
    k_head<<<GG, 128>>>(h1w, h1b, h2w, h2b, h3w, h3b, out);
}

// round 13
// speedup vs baseline: 1.7256x; 1.7256x over previous
#include <cuda_runtime.h>
#include <cuda_bf16.h>

#define NN 50000
#define EE 500000
#define HH 128
#define GG 100
#define NPG 500
#define NPROT 400
#define PNF 35
#define LNF 11
#define DINE 261
#define EPSBN 1e-5f

// ---------------- scratch (static device globals; allocation-free) ----------------
__device__ float g_h[(size_t)NN * HH];
__device__ float g_agg[(size_t)NN * HH];
__device__ float g_P[(size_t)NN * HH];
__device__ float g_Q[(size_t)NN * HH];
__device__ float g_pos[NN * 3];
__device__ float g_posagg[NN * 3];
__device__ float g_deg[NN];
__device__ float g_bnsum[HH];
__device__ float g_bnsq[HH];
// packed bf16 weights (hi/lo split) for m16n8k16 mma: [L][8 ks][16 nt][32 lane][2 reg]
__device__ __align__(16) unsigned g_W2Ph[4 * 8192];
__device__ __align__(16) unsigned g_W2Pl[4 * 8192];
__device__ __align__(16) unsigned g_C1Ph[4 * 8192];
__device__ __align__(16) unsigned g_C1Pl[4 * 8192];

// ---------------- helpers ----------------
union F2 { float2 f; unsigned long long u; };

__device__ __forceinline__ void ffma2(F2& d, F2 a, F2 b) {
    asm("fma.rn.f32x2 %0, %1, %2, %0;" : "+l"(d.u) : "l"(a.u), "l"(b.u));
}
__device__ __forceinline__ float siluf(float x) {
    return x * (1.0f / (1.0f + __expf(-x)));
}
__device__ __forceinline__ float2 silu2(F2 v) {
    return make_float2(siluf(v.f.x), siluf(v.f.y));
}
// pack two fp32 to bf16x2: first arg -> lower 16 bits
__device__ __forceinline__ unsigned packbf(float lo, float hi) {
    unsigned r;
    asm("cvt.rn.bf16x2.f32 %0, %1, %2;" : "=r"(r) : "f"(hi), "f"(lo));
    return r;
}
__device__ __forceinline__ float bfres(float x) {
    return x - __bfloat162float(__float2bfloat16(x));
}

__device__ __forceinline__ void mma_bf16(float* c, unsigned a0, unsigned a1, unsigned a2, unsigned a3,
                                         unsigned b0, unsigned b1) {
    asm volatile("mma.sync.aligned.m16n8k16.row.col.f32.bf16.bf16.f32 "
                 "{%0,%1,%2,%3}, {%4,%5,%6,%7}, {%8,%9}, {%0,%1,%2,%3};"
                 : "+f"(c[0]), "+f"(c[1]), "+f"(c[2]), "+f"(c[3])
                 : "r"(a0), "r"(a1), "r"(a2), "r"(a3), "r"(b0), "r"(b1));
}

// ---------------- setup kernels ----------------
__global__ void k_init(const float* __restrict__ pos) {
    int i = blockIdx.x * blockDim.x + threadIdx.x;
    if (i < NN * 3) g_pos[i] = pos[i];
    if (i < NN) g_deg[i] = 0.0f;
    if (i < HH) { g_bnsum[i] = 0.0f; g_bnsq[i] = 0.0f; }
}

__global__ void k_deg(const int* __restrict__ ei) {
    int i = blockIdx.x * blockDim.x + threadIdx.x;
    if (i < EE) atomicAdd(&g_deg[ei[i]], 1.0f);
}

__global__ void __launch_bounds__(128) k_proj(const float* __restrict__ x,
                                              const float* __restrict__ Wp, const float* __restrict__ bp,
                                              const float* __restrict__ Wl, const float* __restrict__ bl) {
    __shared__ float xs[64][PNF];
    const int tid = threadIdx.x;
    const int base = blockIdx.x * 64;
    for (int i = tid; i < 64 * PNF; i += 128) {
        int n = i / PNF, k = i - n * PNF;
        xs[n][k] = (base + n < NN) ? x[(size_t)(base + n) * PNF + k] : 0.0f;
    }
    __syncthreads();
    float s = 0.0f, sq = 0.0f;
    for (int n = 0; n < 64; n++) {
        int gn = base + n;
        if (gn >= NN) break;
        bool prot = (gn % NPG) < NPROT;
        float acc;
        if (prot) {
            acc = bp[tid];
            #pragma unroll
            for (int k = 0; k < PNF; k++) acc += xs[n][k] * Wp[k * HH + tid];
        } else {
            acc = bl[tid];
            #pragma unroll
            for (int k = 0; k < LNF; k++) acc += xs[n][k] * Wl[k * HH + tid];
        }
        g_h[(size_t)gn * HH + tid] = acc;
        s += acc;
        sq += acc * acc;
    }
    atomicAdd(&g_bnsum[tid], s);
    atomicAdd(&g_bnsq[tid], sq);
}

__global__ void k_bn(const float* __restrict__ gamma, const float* __restrict__ beta) {
    size_t i = (size_t)blockIdx.x * blockDim.x + threadIdx.x;
    if (i >= (size_t)NN * HH) return;
    int t = (int)(i & (HH - 1));
    float mu = g_bnsum[t] * (1.0f / NN);
    float var = g_bnsq[t] * (1.0f / NN) - mu * mu;
    g_h[i] = (g_h[i] - mu) * rsqrtf(var + EPSBN) * gamma[t] + beta[t];
}

__global__ void k_zero() {
    size_t i = (size_t)blockIdx.x * blockDim.x + threadIdx.x;
    if (i < (size_t)NN * HH) g_agg[i] = 0.0f;
    if (i < NN * 3) g_posagg[i] = 0.0f;
}

// pack e_w2 / c_w1 into m16n8k16 B-fragment order, bf16 hi/lo split.
// q = ks*1024 + nt*64 + lane*2 + r ; element pair k0=16ks+2tq+8r (+1), n=8nt+gq
__global__ void k_pack(const float* __restrict__ ew2, const float* __restrict__ cw1) {
    int idx = blockIdx.x * blockDim.x + threadIdx.x;
    if (idx >= 2 * 4 * 8192) return;
    int mat = idx >> 15;
    int l = (idx >> 13) & 3;
    int q = idx & 8191;
    int r = q & 1;
    int lane = (q >> 1) & 31;
    int nt = (q >> 6) & 15;
    int ks = q >> 10;
    int tq = lane & 3, gq = lane >> 2;
    int k0 = 16 * ks + 2 * tq + 8 * r;
    int n = 8 * nt + gq;
    const float* src = mat ? cw1 : ew2;
    float v0 = src[(size_t)l * 16384 + (size_t)k0 * 128 + n];
    float v1 = src[(size_t)l * 16384 + (size_t)(k0 + 1) * 128 + n];
    unsigned hi = packbf(v0, v1);
    unsigned lo = packbf(bfres(v0), bfres(v1));
    size_t off = (size_t)l * 8192 + q;
    if (mat == 0) { g_W2Ph[off] = hi; g_W2Pl[off] = lo; }
    else          { g_C1Ph[off] = hi; g_C1Pl[off] = lo; }
}

// ---------------- per-layer node precompute: P = h@W1a + b1, Q = h@W1b ----------------
__global__ void __launch_bounds__(128) k_nodepre(const float* __restrict__ W1,
                                                 const float* __restrict__ b1) {
    __shared__ float2 Hs[16 * 128];
    const int tid = threadIdx.x;
    const int base = blockIdx.x * 32;
    #pragma unroll 4
    for (int p = 0; p < 16; p++) {
        int n0 = base + 2 * p, n1 = base + 2 * p + 1;
        if (n0 > NN - 1) n0 = NN - 1;
        if (n1 > NN - 1) n1 = NN - 1;
        Hs[p * 128 + tid] = make_float2(g_h[(size_t)n0 * HH + tid], g_h[(size_t)n1 * HH + tid]);
    }
    __syncthreads();
    const int ln = tid & 31;
    const int pg = (tid >> 5) * 4;
    F2 acc[16];

    #pragma unroll
    for (int j = 0; j < 4; j++) {
        float b = b1[ln + 32 * j];
        #pragma unroll
        for (int p = 0; p < 4; p++) acc[p * 4 + j].f = make_float2(b, b);
    }
    #pragma unroll 2
    for (int k = 0; k < 128; k++) {
        F2 w[4];
        #pragma unroll
        for (int j = 0; j < 4; j++) { float v = W1[k * HH + ln + 32 * j]; w[j].f = make_float2(v, v); }
        #pragma unroll
        for (int p = 0; p < 4; p++) {
            F2 v; v.f = Hs[(pg + p) * 128 + k];
            #pragma unroll
            for (int j = 0; j < 4; j++) ffma2(acc[p * 4 + j], v, w[j]);
        }
    }
    #pragma unroll
    for (int p = 0; p < 4; p++) {
        int n0 = base + 2 * (pg + p), n1 = n0 + 1;
        #pragma unroll
        for (int j = 0; j < 4; j++) {
            if (n0 < NN) g_P[(size_t)n0 * HH + ln + 32 * j] = acc[p * 4 + j].f.x;
            if (n1 < NN) g_P[(size_t)n1 * HH + ln + 32 * j] = acc[p * 4 + j].f.y;
        }
    }

    #pragma unroll
    for (int i = 0; i < 16; i++) acc[i].f = make_float2(0.0f, 0.0f);
    const float* W1b = W1 + 128 * HH;
    #pragma unroll 2
    for (int k = 0; k < 128; k++) {
        F2 w[4];
        #pragma unroll
        for (int j = 0; j < 4; j++) { float v = W1b[k * HH + ln + 32 * j]; w[j].f = make_float2(v, v); }
        #pragma unroll
        for (int p = 0; p < 4; p++) {
            F2 v; v.f = Hs[(pg + p) * 128 + k];
            #pragma unroll
            for (int j = 0; j < 4; j++) ffma2(acc[p * 4 + j], v, w[j]);
        }
    }
    #pragma unroll
    for (int p = 0; p < 4; p++) {
        int n0 = base + 2 * (pg + p), n1 = n0 + 1;
        #pragma unroll
        for (int j = 0; j < 4; j++) {
            if (n0 < NN) g_Q[(size_t)n0 * HH + ln + 32 * j] = acc[p * 4 + j].f.x;
            if (n1 < NN) g_Q[(size_t)n1 * HH + ln + 32 * j] = acc[p * 4 + j].f.y;
        }
    }
}

// ---------------- fused edge kernel (bf16 HMMA + 2-way split compensation) ----------------
// 32 edges/block, 128 threads = 4 warps. Warp w: m-tile (w&1)*16, n-range (w>>1)*64.
__global__ void __launch_bounds__(128) k_edge(
    const int* __restrict__ ei, const float* __restrict__ eattr,
    const float* __restrict__ W1tail,
    const float* __restrict__ b2, const float* __restrict__ cb1,
    const float* __restrict__ C2, int layer) {
    __shared__ float sA[32][132];
    __shared__ float sM[32][132];
    __shared__ float sREL[3][32];
    __shared__ float sD2[32];
    __shared__ float sEA[4][32];
    __shared__ float WS[32];
    __shared__ int RI[32], CI[32];

    const int tid = threadIdx.x;
    const int eb = blockIdx.x * 32;

    if (tid < 32) { RI[tid] = ei[eb + tid]; CI[tid] = ei[EE + eb + tid]; }
    {
        int e = tid >> 2, j = tid & 3;
        sEA[j][e] = eattr[(size_t)eb * 4 + tid];
    }
    __syncthreads();

    if (tid < 32) {
        int r = RI[tid], c = CI[tid];
        float rx = g_pos[r * 3 + 0] - g_pos[c * 3 + 0];
        float ry = g_pos[r * 3 + 1] - g_pos[c * 3 + 1];
        float rz = g_pos[r * 3 + 2] - g_pos[c * 3 + 2];
        sREL[0][tid] = rx; sREL[1][tid] = ry; sREL[2][tid] = rz;
        sD2[tid] = rx * rx + ry * ry + rz * rz;
    }
    __syncthreads();

    // ---- hid phase: thread = feature
    {
        float wd  = W1tail[tid];
        float we0 = W1tail[128 + tid];
        float we1 = W1tail[256 + tid];
        float we2 = W1tail[384 + tid];
        float we3 = W1tail[512 + tid];
        #pragma unroll 4
        for (int e = 0; e < 32; e++) {
            int r = RI[e], c = CI[e];
            float v = g_P[(size_t)r * HH + tid] + g_Q[(size_t)c * HH + tid]
                    + sD2[e] * wd + sEA[0][e] * we0 + sEA[1][e] * we1
                    + sEA[2][e] * we2 + sEA[3][e] * we3;
            sA[e][tid] = siluf(v);
        }
    }
    __syncthreads();

    const int lane = tid & 31;
    const int w = tid >> 5;
    const int mb = (w & 1) * 16;
    const int nb = (w >> 1) * 64;
    const int gq = lane >> 2;
    const int tq = lane & 3;
    const unsigned* W2h = g_W2Ph + (size_t)layer * 8192;
    const unsigned* W2l = g_W2Pl + (size_t)layer * 8192;
    const unsigned* C1h = g_C1Ph + (size_t)layer * 8192;
    const unsigned* C1l = g_C1Pl + (size_t)layer * 8192;
    const int ntb = nb >> 3;

    float acc[8][4];

    // ---- GEMM2: m = silu(hid @ W2 + b2)
    #pragma unroll
    for (int j = 0; j < 8; j++)
        #pragma unroll
        for (int i = 0; i < 4; i++) acc[j][i] = 0.0f;
    #pragma unroll
    for (int ks = 0; ks < 8; ks++) {
        int c0 = 16 * ks + 2 * tq;
        float2 p0 = *(const float2*)&sA[mb + gq][c0];
        float2 p1 = *(const float2*)&sA[mb + gq + 8][c0];
        float2 p2 = *(const float2*)&sA[mb + gq][c0 + 8];
        float2 p3 = *(const float2*)&sA[mb + gq + 8][c0 + 8];
        unsigned h0 = packbf(p0.x, p0.y), h1 = packbf(p1.x, p1.y);
        unsigned h2 = packbf(p2.x, p2.y), h3 = packbf(p3.x, p3.y);
        unsigned l0 = packbf(bfres(p0.x), bfres(p0.y)), l1 = packbf(bfres(p1.x), bfres(p1.y));
        unsigned l2 = packbf(bfres(p2.x), bfres(p2.y)), l3 = packbf(bfres(p3.x), bfres(p3.y));
        #pragma unroll
        for (int j = 0; j < 8; j++) {
            size_t boff = (size_t)(ks * 16 + ntb + j) * 64 + lane * 2;
            uint2 bh = *(const uint2*)&W2h[boff];
            uint2 bl = *(const uint2*)&W2l[boff];
            mma_bf16(acc[j], h0, h1, h2, h3, bh.x, bh.y);
            mma_bf16(acc[j], l0, l1, l2, l3, bh.x, bh.y);
            mma_bf16(acc[j], h0, h1, h2, h3, bl.x, bl.y);
        }
    }
    #pragma unroll
    for (int j = 0; j < 8; j++) {
        int n0 = nb + 8 * j + 2 * tq;
        float bA = b2[n0], bB = b2[n0 + 1];
        sM[mb + gq][n0]         = siluf(acc[j][0] + bA);
        sM[mb + gq][n0 + 1]     = siluf(acc[j][1] + bB);
        sM[mb + gq + 8][n0]     = siluf(acc[j][2] + bA);
        sM[mb + gq + 8][n0 + 1] = siluf(acc[j][3] + bB);
    }
    __syncthreads();

    // ---- C1 GEMM: gh = silu(m @ C1 + cb1) -> sA
    #pragma unroll
    for (int j = 0; j < 8; j++)
        #pragma unroll
        for (int i = 0; i < 4; i++) acc[j][i] = 0.0f;
    #pragma unroll
    for (int ks = 0; ks < 8; ks++) {
        int c0 = 16 * ks + 2 * tq;
        float2 p0 = *(const float2*)&sM[mb + gq][c0];
        float2 p1 = *(const float2*)&sM[mb + gq + 8][c0];
        float2 p2 = *(const float2*)&sM[mb + gq][c0 + 8];
        float2 p3 = *(const float2*)&sM[mb + gq + 8][c0 + 8];
        unsigned h0 = packbf(p0.x, p0.y), h1 = packbf(p1.x, p1.y);
        unsigned h2 = packbf(p2.x, p2.y), h3 = packbf(p3.x, p3.y);
        unsigned l0 = packbf(bfres(p0.x), bfres(p0.y)), l1 = packbf(bfres(p1.x), bfres(p1.y));
        unsigned l2 = packbf(bfres(p2.x), bfres(p2.y)), l3 = packbf(bfres(p3.x), bfres(p3.y));
        #pragma unroll
        for (int j = 0; j < 8; j++) {
            size_t boff = (size_t)(ks * 16 + ntb + j) * 64 + lane * 2;
            uint2 bh = *(const uint2*)&C1h[boff];
            uint2 bl = *(const uint2*)&C1l[boff];
            mma_bf16(acc[j], h0, h1, h2, h3, bh.x, bh.y);
            mma_bf16(acc[j], l0, l1, l2, l3, bh.x, bh.y);
            mma_bf16(acc[j], h0, h1, h2, h3, bl.x, bl.y);
        }
    }
    #pragma unroll
    for (int j = 0; j < 8; j++) {
        int n0 = nb + 8 * j + 2 * tq;
        float bA = cb1[n0], bB = cb1[n0 + 1];
        sA[mb + gq][n0]         = siluf(acc[j][0] + bA);
        sA[mb + gq][n0 + 1]     = siluf(acc[j][1] + bB);
        sA[mb + gq + 8][n0]     = siluf(acc[j][2] + bA);
        sA[mb + gq + 8][n0 + 1] = siluf(acc[j][3] + bB);
    }
    __syncthreads();

    // ---- w_e = gh . C2 (warp w handles edges 8w..8w+7)
    {
        float c2a = C2[lane], c2b = C2[lane + 32], c2c = C2[lane + 64], c2d = C2[lane + 96];
        #pragma unroll
        for (int i = 0; i < 8; i++) {
            int e = w * 8 + i;
            float s = sA[e][lane] * c2a + sA[e][lane + 32] * c2b
                    + sA[e][lane + 64] * c2c + sA[e][lane + 96] * c2d;
            #pragma unroll
            for (int o = 16; o; o >>= 1) s += __shfl_xor_sync(0xffffffffu, s, o);
            if (lane == 0) WS[e] = s;
        }
    }
    __syncthreads();

    // ---- scatter: agg[row] += m ; posagg[row] += rel * w
    #pragma unroll 4
    for (int e = 0; e < 32; e++) {
        atomicAdd(&g_agg[(size_t)RI[e] * HH + tid], sM[e][tid]);
    }
    if (tid < 96) {
        int e = tid / 3, c = tid - 3 * e;
        atomicAdd(&g_posagg[RI[e] * 3 + c], sREL[c][e] * WS[e]);
    }
}

// ---------------- fused node kernel ----------------
__global__ void __launch_bounds__(128) k_node(
    const float* __restrict__ NW1, const float* __restrict__ nb1,
    const float* __restrict__ NW2, const float* __restrict__ nb2) {
    __shared__ float2 A[16 * 128];
    __shared__ float2 Bs[16 * 128];
    const int tid = threadIdx.x;
    const int base = blockIdx.x * 32;

    if (tid < 96) {
        int n = base + tid / 3, c = tid % 3;
        if (n < NN) {
            float d = fmaxf(g_deg[n], 1.0f);
            g_pos[n * 3 + c] += g_posagg[n * 3 + c] / d;
        }
    }

    #pragma unroll 4
    for (int p = 0; p < 16; p++) {
        int n0 = base + 2 * p, n1 = base + 2 * p + 1;
        if (n0 > NN - 1) n0 = NN - 1;
        if (n1 > NN - 1) n1 = NN - 1;
        A[p * 128 + tid]  = make_float2(g_h[(size_t)n0 * HH + tid], g_h[(size_t)n1 * HH + tid]);
        Bs[p * 128 + tid] = make_float2(g_agg[(size_t)n0 * HH + tid], g_agg[(size_t)n1 * HH + tid]);
    }
    __syncthreads();

    const int ln = tid & 31;
    const int pg = (tid >> 5) * 4;
    F2 acc[16];

    #pragma unroll
    for (int j = 0; j < 4; j++) {
        float b = nb1[ln + 32 * j];
        #pragma unroll
        for (int p = 0; p < 4; p++) acc[p * 4 + j].f = make_float2(b, b);
    }
    #pragma unroll 2
    for (int k = 0; k < 128; k++) {
        F2 w[4];
        #pragma unroll
        for (int j = 0; j < 4; j++) { float v = NW1[k * HH + ln + 32 * j]; w[j].f = make_float2(v, v); }
        #pragma unroll
        for (int p = 0; p < 4; p++) {
            F2 v; v.f = A[(pg + p) * 128 + k];
            #pragma unroll
            for (int j = 0; j < 4; j++) ffma2(acc[p * 4 + j], v, w[j]);
        }
    }
    #pragma unroll 2
    for (int k = 0; k < 128; k++) {
        F2 w[4];
        #pragma unroll
        for (int j = 0; j < 4; j++) { float v = NW1[(128 + k) * HH + ln + 32 * j]; w[j].f = make_float2(v, v); }
        #pragma unroll
        for (int p = 0; p < 4; p++) {
            F2 v; v.f = Bs[(pg + p) * 128 + k];
            #pragma unroll
            for (int j = 0; j < 4; j++) ffma2(acc[p * 4 + j], v, w[j]);
        }
    }
    __syncthreads();
    #pragma unroll
    for (int p = 0; p < 4; p++)
        #pragma unroll
        for (int j = 0; j < 4; j++)
            Bs[(pg + p) * 128 + ln + 32 * j] = silu2(acc[p * 4 + j]);
    __syncthreads();

    #pragma unroll
    for (int j = 0; j < 4; j++) {
        float b = nb2[ln + 32 * j];
        #pragma unroll
        for (int p = 0; p < 4; p++) acc[p * 4 + j].f = make_float2(b, b);
    }
    #pragma unroll 2
    for (int k = 0; k < 128; k++) {
        F2 w[4];
        #pragma unroll
        for (int j = 0; j < 4; j++) { float v = NW2[k * HH + ln + 32 * j]; w[j].f = make_float2(v, v); }
        #pragma unroll
        for (int p = 0; p < 4; p++) {
            F2 v; v.f = Bs[(pg + p) * 128 + k];
            #pragma unroll
            for (int j = 0; j < 4; j++) ffma2(acc[p * 4 + j], v, w[j]);
        }
    }
    #pragma unroll
    for (int p = 0; p < 4; p++) {
        int n0 = base + 2 * (pg + p), n1 = n0 + 1;
        #pragma unroll
        for (int j = 0; j < 4; j++) {
            if (n0 < NN) g_h[(size_t)n0 * HH + ln + 32 * j] += acc[p * 4 + j].f.x;
            if (n1 < NN) g_h[(size_t)n1 * HH + ln + 32 * j] += acc[p * 4 + j].f.y;
        }
    }
}

// ---------------- pooling + MLP head ----------------
__global__ void __launch_bounds__(128) k_head(
    const float* __restrict__ h1w, const float* __restrict__ h1b,
    const float* __restrict__ h2w, const float* __restrict__ h2b,
    const float* __restrict__ h3w, const float* __restrict__ h3b,
    float* __restrict__ out) {
    __shared__ float gf[256];
    __shared__ float z1[128];
    __shared__ float z2[64];
    const int g = blockIdx.x, t = threadIdx.x;
    const float* hp = g_h + (size_t)g * NPG * HH;
    float s = 0.0f;
    #pragma unroll 4
    for (int i = 0; i < NPG; i++) s += hp[(size_t)i * HH + t];
    gf[t] = s;
    gf[128 + t] = s * (1.0f / (float)NPG);
    __syncthreads();
    float acc = h1b[t];
    #pragma unroll 4
    for (int k = 0; k < 256; k++) acc += gf[k] * h1w[k * 128 + t];
    z1[t] = fmaxf(acc, 0.0f);
    __syncthreads();
    if (t < 64) {
        float a = h2b[t];
        #pragma unroll 4
        for (int k = 0; k < 128; k++) a += z1[k] * h2w[k * 64 + t];
        z2[t] = fmaxf(a, 0.0f);
    }
    __syncthreads();
    if (t == 0) {
        float a = h3b[0];
        #pragma unroll
        for (int k = 0; k < 64; k++) a += z2[k] * h3w[k];
        out[g] = a;
    }
}

// ---------------- launcher ----------------
extern "C" void kernel_launch(void* const* d_in, const int* in_sizes, int n_in,
                              void* d_out, int out_size) {
    const float* x    = (const float*)d_in[0];
    const float* pos  = (const float*)d_in[1];
    const int*   ei   = (const int*)d_in[2];
    const float* ea   = (const float*)d_in[3];
    const float* Wp   = (const float*)d_in[6];
    const float* bp   = (const float*)d_in[7];
    const float* Wl   = (const float*)d_in[8];
    const float* bl   = (const float*)d_in[9];
    const float* gam  = (const float*)d_in[10];
    const float* bet  = (const float*)d_in[11];
    const float* ew1  = (const float*)d_in[12];
    const float* eb1  = (const float*)d_in[13];
    const float* ew2  = (const float*)d_in[14];
    const float* eb2  = (const float*)d_in[15];
    const float* cw1  = (const float*)d_in[16];
    const float* cb1  = (const float*)d_in[17];
    const float* cw2  = (const float*)d_in[18];
    const float* nw1  = (const float*)d_in[19];
    const float* nb1  = (const float*)d_in[20];
    const float* nw2  = (const float*)d_in[21];
    const float* nb2  = (const float*)d_in[22];
    const float* h1w  = (const float*)d_in[23];
    const float* h1b  = (const float*)d_in[24];
    const float* h2w  = (const float*)d_in[25];
    const float* h2b  = (const float*)d_in[26];
    const float* h3w  = (const float*)d_in[27];
    const float* h3b  = (const float*)d_in[28];
    float* out = (float*)d_out;

    k_init<<<(NN * 3 + 255) / 256, 256>>>(pos);
    k_proj<<<(NN + 63) / 64, 128>>>(x, Wp, bp, Wl, bl);
    k_deg<<<(EE + 255) / 256, 256>>>(ei);
    k_bn<<<(int)(((size_t)NN * HH + 255) / 256), 256>>>(gam, bet);
    k_pack<<<(2 * 4 * 8192 + 255) / 256, 256>>>(ew2, cw1);

    for (int l = 0; l < 4; l++) {
        k_zero<<<(int)(((size_t)NN * HH + 255) / 256), 256>>>();
        k_nodepre<<<(NN + 31) / 32, 128>>>(ew1 + (size_t)l * DINE * HH, eb1 + l * HH);
        k_edge<<<EE / 32, 128>>>(ei, ea,
                                 ew1 + (size_t)l * DINE * HH + 256 * HH,
                                 eb2 + l * HH, cb1 + l * HH,
                                 cw2 + (size_t)l * HH, l);
        k_node<<<(NN + 31) / 32, 128>>>(nw1 + (size_t)l * 2 * HH * HH, nb1 + l * HH,
                                        nw2 + (size_t)l * HH * HH,     nb2 + l * HH);
    }
    k_head<<<GG, 128>>>(h1w, h1b, h2w, h2b, h3w, h3b, out);
}